// round 1
// baseline (speedup 1.0000x reference)
#include <cuda_runtime.h>
#include <math.h>

#define N_TOK   32768
#define EDIM    32
#define KCODES  8192
#define MT      128            // tokens per CTA
#define NT      128            // codes per smem tile
#define NTHREADS 256
#define NCTA    (N_TOK / MT)   // 256
#define L2EPS   1e-12f

#define OFF_IDX  (N_TOK * EDIM)          // 1048576
#define OFF_LOSS (OFF_IDX + N_TOK)       // 1081344

// scratch (no cudaMalloc allowed)
__device__ float g_emb_n[KCODES * EDIM];   // L2-normalized codebook, row-major
__device__ float g_ck[KCODES];             // ||e_k||^2 computed like the reference (fp32 of normalized row)
__device__ float g_partial[NCTA];          // per-CTA loss partial sums

// ---------------------------------------------------------------------------
// Kernel 1: normalize codebook rows, compute ||e||^2 of the normalized rows.
// One warp per code (lane == dim), strided over codes.
// ---------------------------------------------------------------------------
__global__ void norm_codebook_kernel(const float* __restrict__ emb) {
    int gwarp  = (blockIdx.x * blockDim.x + threadIdx.x) >> 5;
    int lane   = threadIdx.x & 31;
    int nwarps = (gridDim.x * blockDim.x) >> 5;
    for (int c = gwarp; c < KCODES; c += nwarps) {
        float v = emb[c * EDIM + lane];
        float s = v * v;
        #pragma unroll
        for (int o = 16; o; o >>= 1) s += __shfl_xor_sync(0xffffffffu, s, o);
        float rn = 1.0f / sqrtf(s + L2EPS);
        float en = v * rn;
        g_emb_n[c * EDIM + lane] = en;
        float s2 = en * en;
        #pragma unroll
        for (int o = 16; o; o >>= 1) s2 += __shfl_xor_sync(0xffffffffu, s2, o);
        if (lane == 0) g_ck[c] = s2;
    }
}

// ---------------------------------------------------------------------------
// Kernel 2: fused distance GEMM + argmin + gather + z_q + loss partials.
// CTA: 128 tokens. Thread grid 16(ty) x 16(tx), each thread an 8x8 tile.
// zs/es stored k-major so compute loads are float4 and conflict-free.
// ---------------------------------------------------------------------------
__global__ __launch_bounds__(NTHREADS, 2)
void vq_main_kernel(const float* __restrict__ h,
                    const float* __restrict__ emb_raw,
                    float* __restrict__ out) {
    __shared__ float zs[EDIM][MT];   // normalized tokens, transposed  (16 KB)
    __shared__ float es[EDIM][NT];   // normalized codes tile, transposed (16 KB)
    __shared__ float cks[NT];
    __shared__ float lred[8];

    const int t0   = blockIdx.x * MT;
    const int tid  = threadIdx.x;
    const int warp = tid >> 5;
    const int lane = tid & 31;

    // --- load + L2-normalize this CTA's 128 tokens (lane == dim) ---
    for (int r = warp; r < MT; r += 8) {
        float v = h[(size_t)(t0 + r) * EDIM + lane];
        float s = v * v;
        #pragma unroll
        for (int o = 16; o; o >>= 1) s += __shfl_xor_sync(0xffffffffu, s, o);
        float rn = 1.0f / sqrtf(s + L2EPS);
        zs[lane][r] = v * rn;
    }
    __syncthreads();

    const int ty = tid >> 4;   // token-tile row   (0..15) -> tokens ty*8..+8
    const int tx = tid & 15;   // code-tile column (0..15) -> codes  tx*8..+8

    float best[8];
    int   bidx[8];
    #pragma unroll
    for (int i = 0; i < 8; i++) { best[i] = 3.0e38f; bidx[i] = 0; }

    for (int c0 = 0; c0 < KCODES; c0 += NT) {
        // --- stage code tile (transposed) ---
        #pragma unroll
        for (int it = 0; it < (NT * EDIM / 4) / NTHREADS; it++) {   // 4 float4 per thread
            int idx = tid + it * NTHREADS;          // 0..1023
            int cc  = idx >> 3;                     // code within tile
            int kq  = (idx & 7) * 4;                // k quad
            float4 v = *reinterpret_cast<const float4*>(&g_emb_n[(size_t)(c0 + cc) * EDIM + kq]);
            es[kq + 0][cc] = v.x;
            es[kq + 1][cc] = v.y;
            es[kq + 2][cc] = v.z;
            es[kq + 3][cc] = v.w;
        }
        if (tid < NT) cks[tid] = g_ck[c0 + tid];
        __syncthreads();

        // --- 128x128 dot tile, 8x8 per thread ---
        float acc[8][8];
        #pragma unroll
        for (int i = 0; i < 8; i++)
            #pragma unroll
            for (int j = 0; j < 8; j++) acc[i][j] = 0.f;

        #pragma unroll 8
        for (int k = 0; k < EDIM; k++) {
            float4 a0 = *reinterpret_cast<const float4*>(&zs[k][ty * 8]);
            float4 a1 = *reinterpret_cast<const float4*>(&zs[k][ty * 8 + 4]);
            float4 b0 = *reinterpret_cast<const float4*>(&es[k][tx * 8]);
            float4 b1 = *reinterpret_cast<const float4*>(&es[k][tx * 8 + 4]);
            float za[8] = {a0.x, a0.y, a0.z, a0.w, a1.x, a1.y, a1.z, a1.w};
            float eb[8] = {b0.x, b0.y, b0.z, b0.w, b1.x, b1.y, b1.z, b1.w};
            #pragma unroll
            for (int i = 0; i < 8; i++)
                #pragma unroll
                for (int j = 0; j < 8; j++)
                    acc[i][j] = fmaf(za[i], eb[j], acc[i][j]);
        }

        // --- fold into running argmin (codes ascend; strict < keeps first) ---
        #pragma unroll
        for (int j = 0; j < 8; j++) {
            float ck  = cks[tx * 8 + j];
            int   cid = c0 + tx * 8 + j;
            #pragma unroll
            for (int i = 0; i < 8; i++) {
                float d = fmaf(-2.0f, acc[i][j], ck);
                if (d < best[i]) { best[i] = d; bidx[i] = cid; }
            }
        }
        __syncthreads();   // protect es before next tile's stage
    }

    // --- cross-thread argmin merge (16 tx shards per token), reuse es ---
    float* esf = &es[0][0];
    float* rd  = esf;                                // [MT][16]
    int*   ri  = reinterpret_cast<int*>(esf + MT * 16);
    #pragma unroll
    for (int i = 0; i < 8; i++) {
        int r = ty * 8 + i;
        rd[r * 16 + tx] = best[i];
        ri[r * 16 + tx] = bidx[i];
    }
    __syncthreads();

    float lsum = 0.f;
    if (tid < MT) {
        int t = tid;
        float bd = rd[t * 16];
        int   bi = ri[t * 16];
        #pragma unroll
        for (int j = 1; j < 16; j++) {
            float d  = rd[t * 16 + j];
            int   ix = ri[t * 16 + j];
            if (d < bd || (d == bd && ix < bi)) { bd = d; bi = ix; }
        }
        // gather raw embedding row, renormalize (get_codebook_entry path)
        float v[EDIM];
        float s = 0.f;
        const float4* er = reinterpret_cast<const float4*>(&emb_raw[(size_t)bi * EDIM]);
        #pragma unroll
        for (int q = 0; q < EDIM / 4; q++) {
            float4 f = er[q];
            v[q * 4 + 0] = f.x; v[q * 4 + 1] = f.y;
            v[q * 4 + 2] = f.z; v[q * 4 + 3] = f.w;
            s += f.x * f.x + f.y * f.y + f.z * f.z + f.w * f.w;
        }
        float rn = 1.0f / sqrtf(s + L2EPS);
        #pragma unroll
        for (int d = 0; d < EDIM; d++) {
            float zq = v[d] * rn;
            out[(size_t)(t0 + t) * EDIM + d] = zq;     // straight-through fwd value == z_q
            float diff = zq - zs[d][t];                 // zs == l2_normalize(hidden)
            lsum += diff * diff;
        }
        out[OFF_IDX + t0 + t] = (float)bi;
    }

    // deterministic per-CTA loss partial
    #pragma unroll
    for (int o = 16; o; o >>= 1) lsum += __shfl_xor_sync(0xffffffffu, lsum, o);
    if (lane == 0) lred[warp] = lsum;
    __syncthreads();
    if (tid == 0) {
        float s = 0.f;
        #pragma unroll
        for (int w = 0; w < 8; w++) s += lred[w];
        g_partial[blockIdx.x] = s;
    }
}

// ---------------------------------------------------------------------------
// Kernel 3: reduce partials -> both losses (numerically identical).
// ---------------------------------------------------------------------------
__global__ void finalize_kernel(float* __restrict__ out) {
    __shared__ float sm[8];
    int tid = threadIdx.x;                 // blockDim == NCTA == 256
    float s = g_partial[tid];
    #pragma unroll
    for (int o = 16; o; o >>= 1) s += __shfl_xor_sync(0xffffffffu, s, o);
    if ((tid & 31) == 0) sm[tid >> 5] = s;
    __syncthreads();
    if (tid == 0) {
        float tot = 0.f;
        #pragma unroll
        for (int w = 0; w < 8; w++) tot += sm[w];
        float mean = tot / (float)(N_TOK * EDIM);
        out[OFF_LOSS]     = mean;   // q_latent_loss
        out[OFF_LOSS + 1] = mean;   // e_latent_loss
    }
}

extern "C" void kernel_launch(void* const* d_in, const int* in_sizes, int n_in,
                              void* d_out, int out_size) {
    const float* h   = (const float*)d_in[0];
    const float* emb = (const float*)d_in[1];
    // defensive: if metadata order is embedding-first, swap by size
    if (in_sizes[0] == KCODES * EDIM && in_sizes[1] == N_TOK * EDIM) {
        const float* t = h; h = emb; emb = t;
    }
    float* out = (float*)d_out;

    norm_codebook_kernel<<<32, 256>>>(emb);
    vq_main_kernel<<<NCTA, NTHREADS>>>(h, emb, out);
    finalize_kernel<<<1, NCTA>>>(out);
}

// round 3
// speedup vs baseline: 1.0300x; 1.0300x over previous
#include <cuda_runtime.h>
#include <math.h>

#define N_TOK   32768
#define EDIM    32
#define KCODES  8192
#define MT      128            // tokens per CTA
#define NT      128            // codes per smem tile
#define NTHREADS 256
#define NCTA    (N_TOK / MT)   // 256
#define L2EPS   1e-12f

#define OFF_IDX  (N_TOK * EDIM)          // 1048576
#define OFF_LOSS (OFF_IDX + N_TOK)       // 1081344

// scratch (no cudaMalloc allowed)
__device__ float g_emb_n[KCODES * EDIM];   // L2-normalized codebook, row-major
__device__ float g_ck[KCODES];             // ||e_k||^2 of the normalized rows
__device__ float g_partial[NCTA];          // per-CTA loss partial sums

// ---- packed fp32x2 helpers (sm_103a FFMA2 path) ----------------------------
__device__ __forceinline__ unsigned long long ffma2(unsigned long long a,
                                                    unsigned long long b,
                                                    unsigned long long c) {
    unsigned long long d;
    asm("fma.rn.f32x2 %0, %1, %2, %3;" : "=l"(d) : "l"(a), "l"(b), "l"(c));
    return d;
}
__device__ __forceinline__ unsigned long long dup2(float x) {
    unsigned long long d;
    asm("mov.b64 %0, {%1, %1};" : "=l"(d) : "r"(__float_as_uint(x)));
    return d;
}
__device__ __forceinline__ void unpack2(unsigned long long p, float& lo, float& hi) {
    unsigned int a, b;
    asm("mov.b64 {%0, %1}, %2;" : "=r"(a), "=r"(b) : "l"(p));
    lo = __uint_as_float(a); hi = __uint_as_float(b);
}

// ---------------------------------------------------------------------------
// Kernel 1: normalize codebook rows. One warp per code (lane == dim).
// ---------------------------------------------------------------------------
__global__ void norm_codebook_kernel(const float* __restrict__ emb) {
    int gwarp  = (blockIdx.x * blockDim.x + threadIdx.x) >> 5;
    int lane   = threadIdx.x & 31;
    int nwarps = (gridDim.x * blockDim.x) >> 5;
    for (int c = gwarp; c < KCODES; c += nwarps) {
        float v = emb[c * EDIM + lane];
        float s = v * v;
        #pragma unroll
        for (int o = 16; o; o >>= 1) s += __shfl_xor_sync(0xffffffffu, s, o);
        float rn = 1.0f / sqrtf(s + L2EPS);
        float en = v * rn;
        g_emb_n[c * EDIM + lane] = en;
        float s2 = en * en;
        #pragma unroll
        for (int o = 16; o; o >>= 1) s2 += __shfl_xor_sync(0xffffffffu, s2, o);
        if (lane == 0) g_ck[c] = s2;
    }
}

// ---------------------------------------------------------------------------
// Kernel 2: fused distance GEMM (FFMA2) + argmin + gather + z_q + loss.
// CTA: 128 tokens. Thread (ty,tx) owns 8 tokens x 8 codes; accumulators are
// f32x2-packed along the token dimension (token pairs are adjacent in zs).
// ---------------------------------------------------------------------------
__global__ __launch_bounds__(NTHREADS, 2)
void vq_main_kernel(const float* __restrict__ h,
                    const float* __restrict__ emb_raw,
                    float* __restrict__ out) {
    __shared__ float zs[EDIM][MT];   // normalized tokens, k-major (16 KB)
    __shared__ float es[EDIM][NT];   // normalized code tile, k-major (16 KB)
    __shared__ float cks[NT];
    __shared__ float lred[8];

    const int t0   = blockIdx.x * MT;
    const int tid  = threadIdx.x;
    const int warp = tid >> 5;
    const int lane = tid & 31;

    // --- load + L2-normalize this CTA's 128 tokens (lane == dim) ---
    for (int r = warp; r < MT; r += 8) {
        float v = h[(size_t)(t0 + r) * EDIM + lane];
        float s = v * v;
        #pragma unroll
        for (int o = 16; o; o >>= 1) s += __shfl_xor_sync(0xffffffffu, s, o);
        float rn = 1.0f / sqrtf(s + L2EPS);
        zs[lane][r] = v * rn;
    }
    __syncthreads();

    const int ty = tid >> 4;   // token-tile row   (0..15) -> tokens ty*8..+8
    const int tx = tid & 15;   // code-tile column (0..15) -> codes  tx*8..+8

    float best[8];
    int   bidx[8];
    #pragma unroll
    for (int i = 0; i < 8; i++) { best[i] = 3.0e38f; bidx[i] = 0; }

    for (int c0 = 0; c0 < KCODES; c0 += NT) {
        // --- stage code tile (transposed to k-major) ---
        #pragma unroll
        for (int it = 0; it < (NT * EDIM / 4) / NTHREADS; it++) {   // 4 float4/thread
            int idx = tid + it * NTHREADS;
            int cc  = idx >> 3;
            int kq  = (idx & 7) * 4;
            float4 v = *reinterpret_cast<const float4*>(&g_emb_n[(size_t)(c0 + cc) * EDIM + kq]);
            es[kq + 0][cc] = v.x;
            es[kq + 1][cc] = v.y;
            es[kq + 2][cc] = v.z;
            es[kq + 3][cc] = v.w;
        }
        if (tid < NT) cks[tid] = g_ck[c0 + tid];
        __syncthreads();

        // --- 128x128 dot tile; acc packed (token pair) x 8 codes ---
        unsigned long long acc2[4][8];
        #pragma unroll
        for (int i2 = 0; i2 < 4; i2++)
            #pragma unroll
            for (int j = 0; j < 8; j++) acc2[i2][j] = 0ull;

        #pragma unroll 8
        for (int k = 0; k < EDIM; k++) {
            // token pairs: naturally adjacent in zs -> 4x LDS.64
            const float2* zp = reinterpret_cast<const float2*>(&zs[k][ty * 8]);
            unsigned long long za2[4];
            #pragma unroll
            for (int i2 = 0; i2 < 4; i2++)
                za2[i2] = *reinterpret_cast<const unsigned long long*>(&zp[i2]);

            float4 b0 = *reinterpret_cast<const float4*>(&es[k][tx * 8]);
            float4 b1 = *reinterpret_cast<const float4*>(&es[k][tx * 8 + 4]);
            unsigned long long ebd[8];
            ebd[0] = dup2(b0.x); ebd[1] = dup2(b0.y);
            ebd[2] = dup2(b0.z); ebd[3] = dup2(b0.w);
            ebd[4] = dup2(b1.x); ebd[5] = dup2(b1.y);
            ebd[6] = dup2(b1.z); ebd[7] = dup2(b1.w);

            #pragma unroll
            for (int i2 = 0; i2 < 4; i2++)
                #pragma unroll
                for (int j = 0; j < 8; j++)
                    acc2[i2][j] = ffma2(za2[i2], ebd[j], acc2[i2][j]);
        }

        // --- fold into running argmin (codes ascend; strict < keeps first) ---
        #pragma unroll
        for (int j = 0; j < 8; j++) {
            float ck  = cks[tx * 8 + j];
            int   cid = c0 + tx * 8 + j;
            #pragma unroll
            for (int i2 = 0; i2 < 4; i2++) {
                float dlo, dhi;
                unpack2(acc2[i2][j], dlo, dhi);
                float d0 = fmaf(-2.0f, dlo, ck);
                float d1 = fmaf(-2.0f, dhi, ck);
                if (d0 < best[i2 * 2 + 0]) { best[i2 * 2 + 0] = d0; bidx[i2 * 2 + 0] = cid; }
                if (d1 < best[i2 * 2 + 1]) { best[i2 * 2 + 1] = d1; bidx[i2 * 2 + 1] = cid; }
            }
        }
        __syncthreads();   // protect es before next tile's stage
    }

    // --- cross-thread argmin merge (16 tx shards per token), reuse es ---
    float* esf = &es[0][0];
    float* rd  = esf;                                // [MT][16]
    int*   ri  = reinterpret_cast<int*>(esf + MT * 16);
    #pragma unroll
    for (int i = 0; i < 8; i++) {
        int r = ty * 8 + i;
        rd[r * 16 + tx] = best[i];
        ri[r * 16 + tx] = bidx[i];
    }
    __syncthreads();

    float lsum = 0.f;
    if (tid < MT) {
        int t = tid;
        float bd = rd[t * 16];
        int   bi = ri[t * 16];
        #pragma unroll
        for (int j = 1; j < 16; j++) {
            float d  = rd[t * 16 + j];
            int   ix = ri[t * 16 + j];
            if (d < bd || (d == bd && ix < bi)) { bd = d; bi = ix; }
        }
        // gather raw embedding row, renormalize (get_codebook_entry path)
        float v[EDIM];
        float s = 0.f;
        const float4* er = reinterpret_cast<const float4*>(&emb_raw[(size_t)bi * EDIM]);
        #pragma unroll
        for (int q = 0; q < EDIM / 4; q++) {
            float4 f = er[q];
            v[q * 4 + 0] = f.x; v[q * 4 + 1] = f.y;
            v[q * 4 + 2] = f.z; v[q * 4 + 3] = f.w;
            s += f.x * f.x + f.y * f.y + f.z * f.z + f.w * f.w;
        }
        float rn = 1.0f / sqrtf(s + L2EPS);
        #pragma unroll
        for (int d = 0; d < EDIM; d++) {
            float zq = v[d] * rn;
            out[(size_t)(t0 + t) * EDIM + d] = zq;     // straight-through fwd == z_q
            float diff = zq - zs[d][t];                 // zs == l2_normalize(hidden)
            lsum += diff * diff;
        }
        out[OFF_IDX + t0 + t] = (float)bi;
    }

    // deterministic per-CTA loss partial
    #pragma unroll
    for (int o = 16; o; o >>= 1) lsum += __shfl_xor_sync(0xffffffffu, lsum, o);
    if (lane == 0) lred[warp] = lsum;
    __syncthreads();
    if (tid == 0) {
        float s = 0.f;
        #pragma unroll
        for (int w = 0; w < 8; w++) s += lred[w];
        g_partial[blockIdx.x] = s;
    }
}

// ---------------------------------------------------------------------------
// Kernel 3: reduce partials -> both losses (numerically identical).
// ---------------------------------------------------------------------------
__global__ void finalize_kernel(float* __restrict__ out) {
    __shared__ float sm[8];
    int tid = threadIdx.x;                 // blockDim == NCTA == 256
    float s = g_partial[tid];
    #pragma unroll
    for (int o = 16; o; o >>= 1) s += __shfl_xor_sync(0xffffffffu, s, o);
    if ((tid & 31) == 0) sm[tid >> 5] = s;
    __syncthreads();
    if (tid == 0) {
        float tot = 0.f;
        #pragma unroll
        for (int w = 0; w < 8; w++) tot += sm[w];
        float mean = tot / (float)(N_TOK * EDIM);
        out[OFF_LOSS]     = mean;   // q_latent_loss
        out[OFF_LOSS + 1] = mean;   // e_latent_loss
    }
}

extern "C" void kernel_launch(void* const* d_in, const int* in_sizes, int n_in,
                              void* d_out, int out_size) {
    const float* h   = (const float*)d_in[0];
    const float* emb = (const float*)d_in[1];
    if (in_sizes[0] == KCODES * EDIM && in_sizes[1] == N_TOK * EDIM) {
        const float* t = h; h = emb; emb = t;
    }
    float* out = (float*)d_out;

    norm_codebook_kernel<<<256, 256>>>(emb);
    vq_main_kernel<<<NCTA, NTHREADS>>>(h, emb, out);
    finalize_kernel<<<1, NCTA>>>(out);
}

// round 5
// speedup vs baseline: 2.0517x; 1.9920x over previous
#include <cuda_runtime.h>
#include <cuda_bf16.h>
#include <math.h>

#define N_TOK   32768
#define EDIM    32
#define KCODES  8192
#define MT      128              // tokens per CTA (8 warps x 16)
#define NT      512              // codes per smem tile
#define NBLK    (NT / 8)         // 64 n8-blocks per tile
#define NTILE   (KCODES / NT)    // 16
#define NTHREADS 256
#define NCTA    (N_TOK / MT)     // 256
#define L2EPS   1e-12f

#define OFF_IDX  (N_TOK * EDIM)
#define OFF_LOSS (OFF_IDX + N_TOK)

// dynamic smem byte offsets
#define S_FRAGH 0                // 64 blk * 32 lane * 4 regs * 4B = 32768
#define S_FRAGL 32768
#define S_CKS   65536            // 512 * 4 = 2048 (reused as candidate table)
#define S_ZS    67584            // 32 * 128 * 4 = 16384
#define S_LRED  83968            // 32
#define SMEM_TOTAL 84096

// global scratch (no cudaMalloc allowed)
__device__ unsigned g_fragh[KCODES * 16];   // codebook hi-bf16, HMMA B-fragment layout
__device__ unsigned g_fragl[KCODES * 16];   // codebook lo-bf16 (residual), same layout
__device__ float    g_emb_n[KCODES * EDIM]; // normalized codebook fp32 (exact rescore)
__device__ float    g_ck[KCODES];           // ||e_norm||^2 fp32
__device__ float    g_partial[NCTA];

// ---------------------------------------------------------------------------
// mma.sync m16n8k16 bf16 -> fp32
// ---------------------------------------------------------------------------
__device__ __forceinline__ void mma16816(float* c, const unsigned* a,
                                         unsigned b0, unsigned b1) {
    asm volatile(
        "mma.sync.aligned.m16n8k16.row.col.f32.bf16.bf16.f32 "
        "{%0,%1,%2,%3}, {%4,%5,%6,%7}, {%8,%9}, {%0,%1,%2,%3};"
        : "+f"(c[0]), "+f"(c[1]), "+f"(c[2]), "+f"(c[3])
        : "r"(a[0]), "r"(a[1]), "r"(a[2]), "r"(a[3]), "r"(b0), "r"(b1));
}

__device__ __forceinline__ unsigned pack_split(float v0, float v1,
                                               float& r0, float& r1) {
    __nv_bfloat16 b0 = __float2bfloat16(v0);
    __nv_bfloat16 b1 = __float2bfloat16(v1);
    r0 = v0 - __bfloat162float(b0);
    r1 = v1 - __bfloat162float(b1);
    return (unsigned)__bfloat16_as_ushort(b0) |
           ((unsigned)__bfloat16_as_ushort(b1) << 16);
}

// ---------------------------------------------------------------------------
// Kernel 1: normalize codebook (fp32 copy + ck), split to bf16 hi/lo in HMMA
// B-fragment layout: word = (c/8)*128 + ((c%8)*4 + (p%4))*4 + (p/4), p=k-pair.
// One warp per code (lane == dim).
// ---------------------------------------------------------------------------
__global__ void prep_codebook_kernel(const float* __restrict__ emb) {
    int gwarp  = (blockIdx.x * blockDim.x + threadIdx.x) >> 5;
    int lane   = threadIdx.x & 31;
    int nwarps = (gridDim.x * blockDim.x) >> 5;
    for (int c = gwarp; c < KCODES; c += nwarps) {
        float v = emb[c * EDIM + lane];
        float s = v * v;
        #pragma unroll
        for (int o = 16; o; o >>= 1) s += __shfl_xor_sync(0xffffffffu, s, o);
        float rn = 1.0f / sqrtf(s + L2EPS);
        float en = v * rn;
        g_emb_n[c * EDIM + lane] = en;

        float s2 = en * en;
        #pragma unroll
        for (int o = 16; o; o >>= 1) s2 += __shfl_xor_sync(0xffffffffu, s2, o);
        if (lane == 0) g_ck[c] = s2;

        __nv_bfloat16 bh = __float2bfloat16(en);
        float res = en - __bfloat162float(bh);
        __nv_bfloat16 bl = __float2bfloat16(res);
        unsigned uh = __bfloat16_as_ushort(bh);
        unsigned ul = __bfloat16_as_ushort(bl);

        int p = lane & 15;   // k-pair index 0..15
        unsigned wh = __shfl_sync(0xffffffffu, uh, 2 * p) |
                      (__shfl_sync(0xffffffffu, uh, 2 * p + 1) << 16);
        unsigned wl = __shfl_sync(0xffffffffu, ul, 2 * p) |
                      (__shfl_sync(0xffffffffu, ul, 2 * p + 1) << 16);
        unsigned word = (unsigned)(c >> 3) * 128u +
                        (unsigned)(((c & 7) * 4 + (p & 3)) * 4 + (p >> 2));
        if (lane < 16) g_fragh[word] = wh;
        else           g_fragl[word] = wl;
    }
}

// ---------------------------------------------------------------------------
// Kernel 2: HMMA distance GEMM (4-pass split-bf16) + per-shard argmin +
// exact fp32 rescue + gather + loss.
// ---------------------------------------------------------------------------
__global__ __launch_bounds__(NTHREADS, 2)
void vq_main_kernel(const float* __restrict__ h,
                    const float* __restrict__ emb_raw,
                    float* __restrict__ out) {
    extern __shared__ char smem[];
    unsigned* sfh = (unsigned*)(smem + S_FRAGH);
    unsigned* sfl = (unsigned*)(smem + S_FRAGL);
    float*    sck = (float*)(smem + S_CKS);
    float*    zsf = (float*)(smem + S_ZS);     // [EDIM][MT] k-major
    float*    lred = (float*)(smem + S_LRED);

    const int t0   = blockIdx.x * MT;
    const int tid  = threadIdx.x;
    const int warp = tid >> 5;
    const int lane = tid & 31;
    const int gid  = lane >> 2;     // 0..7
    const int tig  = lane & 3;      // 0..3 (quarter-shard of codes)

    // --- load + L2-normalize 128 tokens (lane == dim) ---
    for (int r = warp; r < MT; r += 8) {
        float v = h[(size_t)(t0 + r) * EDIM + lane];
        float s = v * v;
        #pragma unroll
        for (int o = 16; o; o >>= 1) s += __shfl_xor_sync(0xffffffffu, s, o);
        float rn = 1.0f / sqrtf(s + L2EPS);
        zsf[lane * MT + r] = v * rn;
    }
    __syncthreads();

    // --- build this warp's A fragments (16 tokens x k32, hi + lo) ---
    const int tok0 = warp * 16 + gid;
    const int tok1 = tok0 + 8;
    unsigned ah[8], al[8];
    #pragma unroll
    for (int ks = 0; ks < 2; ks++) {
        int k0 = ks * 16 + 2 * tig;
        int k1 = k0 + 8;
        float r0, r1;
        ah[ks * 4 + 0] = pack_split(zsf[k0 * MT + tok0], zsf[(k0 + 1) * MT + tok0], r0, r1);
        al[ks * 4 + 0] = pack_split(r0, r1, r0, r1);
        ah[ks * 4 + 1] = pack_split(zsf[k0 * MT + tok1], zsf[(k0 + 1) * MT + tok1], r0, r1);
        al[ks * 4 + 1] = pack_split(r0, r1, r0, r1);
        ah[ks * 4 + 2] = pack_split(zsf[k1 * MT + tok0], zsf[(k1 + 1) * MT + tok0], r0, r1);
        al[ks * 4 + 2] = pack_split(r0, r1, r0, r1);
        ah[ks * 4 + 3] = pack_split(zsf[k1 * MT + tok1], zsf[(k1 + 1) * MT + tok1], r0, r1);
        al[ks * 4 + 3] = pack_split(r0, r1, r0, r1);
    }

    float best0 = 3.0e38f, best1 = 3.0e38f;
    int   bidx0 = 0,       bidx1 = 0;

    for (int tl = 0; tl < NTILE; tl++) {
        __syncthreads();
        {
            const float4* gh = (const float4*)(g_fragh + (size_t)tl * NT * 16);
            const float4* gl = (const float4*)(g_fragl + (size_t)tl * NT * 16);
            float4* shh = (float4*)sfh;
            float4* shl = (float4*)sfl;
            #pragma unroll
            for (int i = 0; i < 8; i++) {
                int f = tid + i * NTHREADS;
                shh[f] = gh[f];
                shl[f] = gl[f];
            }
            sck[tid]            = g_ck[tl * NT + tid];
            sck[tid + NTHREADS] = g_ck[tl * NT + tid + NTHREADS];
        }
        __syncthreads();

        const int tbase = tl * NT;
        #pragma unroll 2
        for (int b = 0; b < NBLK; b += 2) {
            uint4 ubh0 = *(const uint4*)&sfh[(b * 32 + lane) * 4];
            uint4 ubl0 = *(const uint4*)&sfl[(b * 32 + lane) * 4];
            uint4 ubh1 = *(const uint4*)&sfh[((b + 1) * 32 + lane) * 4];
            uint4 ubl1 = *(const uint4*)&sfl[((b + 1) * 32 + lane) * 4];

            float accA[4] = {0.f, 0.f, 0.f, 0.f};
            float accB[4] = {0.f, 0.f, 0.f, 0.f};
            // zh*eh
            mma16816(accA, ah,     ubh0.x, ubh0.y);
            mma16816(accA, ah + 4, ubh0.z, ubh0.w);
            mma16816(accB, ah,     ubh1.x, ubh1.y);
            mma16816(accB, ah + 4, ubh1.z, ubh1.w);
            // zh*el
            mma16816(accA, ah,     ubl0.x, ubl0.y);
            mma16816(accA, ah + 4, ubl0.z, ubl0.w);
            mma16816(accB, ah,     ubl1.x, ubl1.y);
            mma16816(accB, ah + 4, ubl1.z, ubl1.w);
            // zl*eh
            mma16816(accA, al,     ubh0.x, ubh0.y);
            mma16816(accA, al + 4, ubh0.z, ubh0.w);
            mma16816(accB, al,     ubh1.x, ubh1.y);
            mma16816(accB, al + 4, ubh1.z, ubh1.w);
            // zl*el  (4th pass: kills the dominant split error)
            mma16816(accA, al,     ubl0.x, ubl0.y);
            mma16816(accA, al + 4, ubl0.z, ubl0.w);
            mma16816(accB, al,     ubl1.x, ubl1.y);
            mma16816(accB, al + 4, ubl1.z, ubl1.w);

            {
                float2 ck2 = *(const float2*)&sck[b * 8 + 2 * tig];
                int cid = tbase + b * 8 + 2 * tig;
                float d;
                d = fmaf(-2.0f, accA[0], ck2.x); if (d < best0) { best0 = d; bidx0 = cid; }
                d = fmaf(-2.0f, accA[1], ck2.y); if (d < best0) { best0 = d; bidx0 = cid + 1; }
                d = fmaf(-2.0f, accA[2], ck2.x); if (d < best1) { best1 = d; bidx1 = cid; }
                d = fmaf(-2.0f, accA[3], ck2.y); if (d < best1) { best1 = d; bidx1 = cid + 1; }
            }
            {
                float2 ck2 = *(const float2*)&sck[(b + 1) * 8 + 2 * tig];
                int cid = tbase + (b + 1) * 8 + 2 * tig;
                float d;
                d = fmaf(-2.0f, accB[0], ck2.x); if (d < best0) { best0 = d; bidx0 = cid; }
                d = fmaf(-2.0f, accB[1], ck2.y); if (d < best0) { best0 = d; bidx0 = cid + 1; }
                d = fmaf(-2.0f, accB[2], ck2.x); if (d < best1) { best1 = d; bidx1 = cid; }
                d = fmaf(-2.0f, accB[3], ck2.y); if (d < best1) { best1 = d; bidx1 = cid + 1; }
            }
        }
    }

    // --- stash the 4 per-shard candidate indices per token (reuse sck) ---
    __syncthreads();                       // all warps done reading sck
    int* cand = (int*)(smem + S_CKS);      // [MT][4]
    cand[tok0 * 4 + tig] = bidx0;
    cand[tok1 * 4 + tig] = bidx1;
    __syncthreads();

    // --- exact fp32 rescore of the 4 candidates + gather + z_q + loss ---
    float lsum = 0.f;
    if (tid < MT) {
        const int t = tid;
        float z[EDIM];
        #pragma unroll
        for (int k = 0; k < EDIM; k++) z[k] = zsf[k * MT + t];

        float bd = 3.0e38f;
        int   bi = KCODES;
        #pragma unroll
        for (int j = 0; j < 4; j++) {
            int c = cand[t * 4 + j];
            float dot = 0.f;
            const float4* en = (const float4*)&g_emb_n[(size_t)c * EDIM];
            #pragma unroll
            for (int q = 0; q < EDIM / 4; q++) {
                float4 e = en[q];
                dot = fmaf(z[q * 4 + 0], e.x, dot);
                dot = fmaf(z[q * 4 + 1], e.y, dot);
                dot = fmaf(z[q * 4 + 2], e.z, dot);
                dot = fmaf(z[q * 4 + 3], e.w, dot);
            }
            float d = fmaf(-2.0f, dot, g_ck[c]);
            if (d < bd || (d == bd && c < bi)) { bd = d; bi = c; }
        }

        // gather raw embedding row, renormalize (get_codebook_entry path)
        float v[EDIM];
        float s = 0.f;
        const float4* er = (const float4*)&emb_raw[(size_t)bi * EDIM];
        #pragma unroll
        for (int q = 0; q < EDIM / 4; q++) {
            float4 f = er[q];
            v[q * 4 + 0] = f.x; v[q * 4 + 1] = f.y;
            v[q * 4 + 2] = f.z; v[q * 4 + 3] = f.w;
            s += f.x * f.x + f.y * f.y + f.z * f.z + f.w * f.w;
        }
        float rn = 1.0f / sqrtf(s + L2EPS);
        float4* ow = (float4*)&out[(size_t)(t0 + t) * EDIM];
        #pragma unroll
        for (int q = 0; q < EDIM / 4; q++) {
            float zq0 = v[q * 4 + 0] * rn, zq1 = v[q * 4 + 1] * rn;
            float zq2 = v[q * 4 + 2] * rn, zq3 = v[q * 4 + 3] * rn;
            ow[q] = make_float4(zq0, zq1, zq2, zq3);
            float d0 = zq0 - z[q * 4 + 0];
            float d1 = zq1 - z[q * 4 + 1];
            float d2 = zq2 - z[q * 4 + 2];
            float d3 = zq3 - z[q * 4 + 3];
            lsum += d0 * d0 + d1 * d1 + d2 * d2 + d3 * d3;
        }
        out[OFF_IDX + t0 + t] = (float)bi;
    }

    // deterministic per-CTA loss partial
    #pragma unroll
    for (int o = 16; o; o >>= 1) lsum += __shfl_xor_sync(0xffffffffu, lsum, o);
    if (lane == 0) lred[warp] = lsum;
    __syncthreads();
    if (tid == 0) {
        float s = 0.f;
        #pragma unroll
        for (int w = 0; w < 8; w++) s += lred[w];
        g_partial[blockIdx.x] = s;
    }
}

// ---------------------------------------------------------------------------
// Kernel 3: reduce partials -> both losses.
// ---------------------------------------------------------------------------
__global__ void finalize_kernel(float* __restrict__ out) {
    __shared__ float sm[8];
    int tid = threadIdx.x;                 // blockDim == 256
    float s = g_partial[tid];
    #pragma unroll
    for (int o = 16; o; o >>= 1) s += __shfl_xor_sync(0xffffffffu, s, o);
    if ((tid & 31) == 0) sm[tid >> 5] = s;
    __syncthreads();
    if (tid == 0) {
        float tot = 0.f;
        #pragma unroll
        for (int w = 0; w < 8; w++) tot += sm[w];
        float mean = tot / (float)(N_TOK * EDIM);
        out[OFF_LOSS]     = mean;
        out[OFF_LOSS + 1] = mean;
    }
}

extern "C" void kernel_launch(void* const* d_in, const int* in_sizes, int n_in,
                              void* d_out, int out_size) {
    const float* h   = (const float*)d_in[0];
    const float* emb = (const float*)d_in[1];
    if (in_sizes[0] == KCODES * EDIM && in_sizes[1] == N_TOK * EDIM) {
        const float* t = h; h = emb; emb = t;
    }
    float* out = (float*)d_out;

    cudaFuncSetAttribute(vq_main_kernel,
                         cudaFuncAttributeMaxDynamicSharedMemorySize, SMEM_TOTAL);

    prep_codebook_kernel<<<256, 256>>>(emb);
    vq_main_kernel<<<NCTA, NTHREADS, SMEM_TOTAL>>>(h, emb, out);
    finalize_kernel<<<1, 256>>>(out);
}

// round 7
// speedup vs baseline: 2.3909x; 1.1653x over previous
#include <cuda_runtime.h>
#include <cuda_fp16.h>
#include <math.h>

#define N_TOK   32768
#define EDIM    32
#define KCODES  8192
#define MT      128              // tokens per CTA (8 warps x 16)
#define NT      512              // codes per smem tile
#define NBLK    (NT / 8)         // 64 n8-blocks per tile
#define NTILE   (KCODES / NT)    // 16
#define NTHREADS 256
#define NCTA    (N_TOK / MT)     // 256
#define L2EPS   1e-12f

#define OFF_IDX  (N_TOK * EDIM)
#define OFF_LOSS (OFF_IDX + N_TOK)

// dynamic smem byte offsets
#define S_FRAGH 0                // 64 blk * 32 lane * 4 regs * 4B = 32768
#define S_FRAGL 32768
#define S_CKS   65536            // 512 * 4 = 2048 (reused as candidate table)
#define S_ZS    67584            // 32 * 128 * 4 = 16384
#define S_LRED  83968            // 32
#define SMEM_TOTAL 84096

// global scratch (no cudaMalloc allowed)
__device__ unsigned g_fragh[KCODES * 16];   // codebook hi-fp16, HMMA B-fragment layout
__device__ unsigned g_fragl[KCODES * 16];   // codebook lo-fp16 (residual), same layout
__device__ float    g_emb_n[KCODES * EDIM]; // normalized codebook fp32 (exact rescore)
__device__ float    g_ck[KCODES];           // ||e_norm||^2 fp32
__device__ float    g_partial[NCTA];

// ---------------------------------------------------------------------------
// mma.sync m16n8k16 fp16 -> fp32
// ---------------------------------------------------------------------------
__device__ __forceinline__ void mma16816(float* c, const unsigned* a,
                                         unsigned b0, unsigned b1) {
    asm volatile(
        "mma.sync.aligned.m16n8k16.row.col.f32.f16.f16.f32 "
        "{%0,%1,%2,%3}, {%4,%5,%6,%7}, {%8,%9}, {%0,%1,%2,%3};"
        : "+f"(c[0]), "+f"(c[1]), "+f"(c[2]), "+f"(c[3])
        : "r"(a[0]), "r"(a[1]), "r"(a[2]), "r"(a[3]), "r"(b0), "r"(b1));
}

__device__ __forceinline__ unsigned pack_split(float v0, float v1,
                                               float& r0, float& r1) {
    __half b0 = __float2half_rn(v0);
    __half b1 = __float2half_rn(v1);
    r0 = v0 - __half2float(b0);
    r1 = v1 - __half2float(b1);
    return (unsigned)__half_as_ushort(b0) |
           ((unsigned)__half_as_ushort(b1) << 16);
}

// ---------------------------------------------------------------------------
// Kernel 1: normalize codebook (fp32 copy + ck), split to fp16 hi/lo in HMMA
// B-fragment layout: word = (c/8)*128 + ((c%8)*4 + (p%4))*4 + (p/4), p=k-pair.
// One warp per code (lane == dim).
// ---------------------------------------------------------------------------
__global__ void prep_codebook_kernel(const float* __restrict__ emb) {
    int gwarp  = (blockIdx.x * blockDim.x + threadIdx.x) >> 5;
    int lane   = threadIdx.x & 31;
    int nwarps = (gridDim.x * blockDim.x) >> 5;
    for (int c = gwarp; c < KCODES; c += nwarps) {
        float v = emb[c * EDIM + lane];
        float s = v * v;
        #pragma unroll
        for (int o = 16; o; o >>= 1) s += __shfl_xor_sync(0xffffffffu, s, o);
        float rn = 1.0f / sqrtf(s + L2EPS);
        float en = v * rn;
        g_emb_n[c * EDIM + lane] = en;

        float s2 = en * en;
        #pragma unroll
        for (int o = 16; o; o >>= 1) s2 += __shfl_xor_sync(0xffffffffu, s2, o);
        if (lane == 0) g_ck[c] = s2;

        __half bh = __float2half_rn(en);
        float res = en - __half2float(bh);
        __half bl = __float2half_rn(res);
        unsigned uh = __half_as_ushort(bh);
        unsigned ul = __half_as_ushort(bl);

        int p = lane & 15;   // k-pair index 0..15
        unsigned wh = __shfl_sync(0xffffffffu, uh, 2 * p) |
                      (__shfl_sync(0xffffffffu, uh, 2 * p + 1) << 16);
        unsigned wl = __shfl_sync(0xffffffffu, ul, 2 * p) |
                      (__shfl_sync(0xffffffffu, ul, 2 * p + 1) << 16);
        unsigned word = (unsigned)(c >> 3) * 128u +
                        (unsigned)(((c & 7) * 4 + (p & 3)) * 4 + (p >> 2));
        if (lane < 16) g_fragh[word] = wh;
        else           g_fragl[word] = wl;
    }
}

// ---------------------------------------------------------------------------
// Kernel 2: HMMA distance GEMM (3-pass split-fp16) + per-shard argmin +
// exact fp32 rescue + gather + loss.
// ---------------------------------------------------------------------------
__global__ __launch_bounds__(NTHREADS, 2)
void vq_main_kernel(const float* __restrict__ h,
                    const float* __restrict__ emb_raw,
                    float* __restrict__ out) {
    extern __shared__ char smem[];
    unsigned* sfh = (unsigned*)(smem + S_FRAGH);
    unsigned* sfl = (unsigned*)(smem + S_FRAGL);
    float*    sck = (float*)(smem + S_CKS);
    float*    zsf = (float*)(smem + S_ZS);     // [EDIM][MT] k-major
    float*    lred = (float*)(smem + S_LRED);

    const int t0   = blockIdx.x * MT;
    const int tid  = threadIdx.x;
    const int warp = tid >> 5;
    const int lane = tid & 31;
    const int gid  = lane >> 2;     // 0..7
    const int tig  = lane & 3;      // 0..3 (quarter-shard of codes)

    // --- load + L2-normalize 128 tokens (lane == dim) ---
    for (int r = warp; r < MT; r += 8) {
        float v = h[(size_t)(t0 + r) * EDIM + lane];
        float s = v * v;
        #pragma unroll
        for (int o = 16; o; o >>= 1) s += __shfl_xor_sync(0xffffffffu, s, o);
        float rn = 1.0f / sqrtf(s + L2EPS);
        zsf[lane * MT + r] = v * rn;
    }
    __syncthreads();

    // --- build this warp's A fragments (16 tokens x k32, hi + lo) ---
    const int tok0 = warp * 16 + gid;
    const int tok1 = tok0 + 8;
    unsigned ah[8], al[8];
    #pragma unroll
    for (int ks = 0; ks < 2; ks++) {
        int k0 = ks * 16 + 2 * tig;
        int k1 = k0 + 8;
        float r0, r1;
        ah[ks * 4 + 0] = pack_split(zsf[k0 * MT + tok0], zsf[(k0 + 1) * MT + tok0], r0, r1);
        al[ks * 4 + 0] = pack_split(r0, r1, r0, r1);
        ah[ks * 4 + 1] = pack_split(zsf[k0 * MT + tok1], zsf[(k0 + 1) * MT + tok1], r0, r1);
        al[ks * 4 + 1] = pack_split(r0, r1, r0, r1);
        ah[ks * 4 + 2] = pack_split(zsf[k1 * MT + tok0], zsf[(k1 + 1) * MT + tok0], r0, r1);
        al[ks * 4 + 2] = pack_split(r0, r1, r0, r1);
        ah[ks * 4 + 3] = pack_split(zsf[k1 * MT + tok1], zsf[(k1 + 1) * MT + tok1], r0, r1);
        al[ks * 4 + 3] = pack_split(r0, r1, r0, r1);
    }

    float best0 = 3.0e38f, best1 = 3.0e38f;
    int   bidx0 = 0,       bidx1 = 0;

    for (int tl = 0; tl < NTILE; tl++) {
        __syncthreads();
        {
            const float4* gh = (const float4*)(g_fragh + (size_t)tl * NT * 16);
            const float4* gl = (const float4*)(g_fragl + (size_t)tl * NT * 16);
            float4* shh = (float4*)sfh;
            float4* shl = (float4*)sfl;
            #pragma unroll
            for (int i = 0; i < 8; i++) {
                int f = tid + i * NTHREADS;
                shh[f] = gh[f];
                shl[f] = gl[f];
            }
            sck[tid]            = g_ck[tl * NT + tid];
            sck[tid + NTHREADS] = g_ck[tl * NT + tid + NTHREADS];
        }
        __syncthreads();

        const int tbase = tl * NT;
        #pragma unroll 2
        for (int b = 0; b < NBLK; b += 2) {
            uint4 ubh0 = *(const uint4*)&sfh[(b * 32 + lane) * 4];
            uint4 ubl0 = *(const uint4*)&sfl[(b * 32 + lane) * 4];
            uint4 ubh1 = *(const uint4*)&sfh[((b + 1) * 32 + lane) * 4];
            uint4 ubl1 = *(const uint4*)&sfl[((b + 1) * 32 + lane) * 4];

            float accA[4] = {0.f, 0.f, 0.f, 0.f};
            float accB[4] = {0.f, 0.f, 0.f, 0.f};
            // zh*eh
            mma16816(accA, ah,     ubh0.x, ubh0.y);
            mma16816(accA, ah + 4, ubh0.z, ubh0.w);
            mma16816(accB, ah,     ubh1.x, ubh1.y);
            mma16816(accB, ah + 4, ubh1.z, ubh1.w);
            // zh*el
            mma16816(accA, ah,     ubl0.x, ubl0.y);
            mma16816(accA, ah + 4, ubl0.z, ubl0.w);
            mma16816(accB, ah,     ubl1.x, ubl1.y);
            mma16816(accB, ah + 4, ubl1.z, ubl1.w);
            // zl*eh   (zl*el dropped: fp16 split residual-product ~6e-8, below
            //          the bf16 4-pass error that already gave zero flips)
            mma16816(accA, al,     ubh0.x, ubh0.y);
            mma16816(accA, al + 4, ubh0.z, ubh0.w);
            mma16816(accB, al,     ubh1.x, ubh1.y);
            mma16816(accB, al + 4, ubh1.z, ubh1.w);

            {
                float2 ck2 = *(const float2*)&sck[b * 8 + 2 * tig];
                int cid = tbase + b * 8 + 2 * tig;
                float d;
                d = fmaf(-2.0f, accA[0], ck2.x); if (d < best0) { best0 = d; bidx0 = cid; }
                d = fmaf(-2.0f, accA[1], ck2.y); if (d < best0) { best0 = d; bidx0 = cid + 1; }
                d = fmaf(-2.0f, accA[2], ck2.x); if (d < best1) { best1 = d; bidx1 = cid; }
                d = fmaf(-2.0f, accA[3], ck2.y); if (d < best1) { best1 = d; bidx1 = cid + 1; }
            }
            {
                float2 ck2 = *(const float2*)&sck[(b + 1) * 8 + 2 * tig];
                int cid = tbase + (b + 1) * 8 + 2 * tig;
                float d;
                d = fmaf(-2.0f, accB[0], ck2.x); if (d < best0) { best0 = d; bidx0 = cid; }
                d = fmaf(-2.0f, accB[1], ck2.y); if (d < best0) { best0 = d; bidx0 = cid + 1; }
                d = fmaf(-2.0f, accB[2], ck2.x); if (d < best1) { best1 = d; bidx1 = cid; }
                d = fmaf(-2.0f, accB[3], ck2.y); if (d < best1) { best1 = d; bidx1 = cid + 1; }
            }
        }
    }

    // --- stash the 4 per-shard candidate indices per token (reuse sck) ---
    __syncthreads();                       // all warps done reading sck
    int* cand = (int*)(smem + S_CKS);      // [MT][4]
    cand[tok0 * 4 + tig] = bidx0;
    cand[tok1 * 4 + tig] = bidx1;
    __syncthreads();

    // --- exact fp32 rescore of the 4 candidates + gather + z_q + loss ---
    float lsum = 0.f;
    if (tid < MT) {
        const int t = tid;
        float z[EDIM];
        #pragma unroll
        for (int k = 0; k < EDIM; k++) z[k] = zsf[k * MT + t];

        float bd = 3.0e38f;
        int   bi = KCODES;
        #pragma unroll
        for (int j = 0; j < 4; j++) {
            int c = cand[t * 4 + j];
            float dot = 0.f;
            const float4* en = (const float4*)&g_emb_n[(size_t)c * EDIM];
            #pragma unroll
            for (int q = 0; q < EDIM / 4; q++) {
                float4 e = en[q];
                dot = fmaf(z[q * 4 + 0], e.x, dot);
                dot = fmaf(z[q * 4 + 1], e.y, dot);
                dot = fmaf(z[q * 4 + 2], e.z, dot);
                dot = fmaf(z[q * 4 + 3], e.w, dot);
            }
            float d = fmaf(-2.0f, dot, g_ck[c]);
            if (d < bd || (d == bd && c < bi)) { bd = d; bi = c; }
        }

        // gather raw embedding row, renormalize (get_codebook_entry path)
        float v[EDIM];
        float s = 0.f;
        const float4* er = (const float4*)&emb_raw[(size_t)bi * EDIM];
        #pragma unroll
        for (int q = 0; q < EDIM / 4; q++) {
            float4 f = er[q];
            v[q * 4 + 0] = f.x; v[q * 4 + 1] = f.y;
            v[q * 4 + 2] = f.z; v[q * 4 + 3] = f.w;
            s += f.x * f.x + f.y * f.y + f.z * f.z + f.w * f.w;
        }
        float rn = 1.0f / sqrtf(s + L2EPS);
        float4* ow = (float4*)&out[(size_t)(t0 + t) * EDIM];
        #pragma unroll
        for (int q = 0; q < EDIM / 4; q++) {
            float zq0 = v[q * 4 + 0] * rn, zq1 = v[q * 4 + 1] * rn;
            float zq2 = v[q * 4 + 2] * rn, zq3 = v[q * 4 + 3] * rn;
            ow[q] = make_float4(zq0, zq1, zq2, zq3);
            float d0 = zq0 - z[q * 4 + 0];
            float d1 = zq1 - z[q * 4 + 1];
            float d2 = zq2 - z[q * 4 + 2];
            float d3 = zq3 - z[q * 4 + 3];
            lsum += d0 * d0 + d1 * d1 + d2 * d2 + d3 * d3;
        }
        out[OFF_IDX + t0 + t] = (float)bi;
    }

    // deterministic per-CTA loss partial
    #pragma unroll
    for (int o = 16; o; o >>= 1) lsum += __shfl_xor_sync(0xffffffffu, lsum, o);
    if (lane == 0) lred[warp] = lsum;
    __syncthreads();
    if (tid == 0) {
        float s = 0.f;
        #pragma unroll
        for (int w = 0; w < 8; w++) s += lred[w];
        g_partial[blockIdx.x] = s;
    }
}

// ---------------------------------------------------------------------------
// Kernel 3: reduce partials -> both losses.
// ---------------------------------------------------------------------------
__global__ void finalize_kernel(float* __restrict__ out) {
    __shared__ float sm[8];
    int tid = threadIdx.x;                 // blockDim == 256
    float s = g_partial[tid];
    #pragma unroll
    for (int o = 16; o; o >>= 1) s += __shfl_xor_sync(0xffffffffu, s, o);
    if ((tid & 31) == 0) sm[tid >> 5] = s;
    __syncthreads();
    if (tid == 0) {
        float tot = 0.f;
        #pragma unroll
        for (int w = 0; w < 8; w++) tot += sm[w];
        float mean = tot / (float)(N_TOK * EDIM);
        out[OFF_LOSS]     = mean;
        out[OFF_LOSS + 1] = mean;
    }
}

extern "C" void kernel_launch(void* const* d_in, const int* in_sizes, int n_in,
                              void* d_out, int out_size) {
    const float* h   = (const float*)d_in[0];
    const float* emb = (const float*)d_in[1];
    if (in_sizes[0] == KCODES * EDIM && in_sizes[1] == N_TOK * EDIM) {
        const float* t = h; h = emb; emb = t;
    }
    float* out = (float*)d_out;

    cudaFuncSetAttribute(vq_main_kernel,
                         cudaFuncAttributeMaxDynamicSharedMemorySize, SMEM_TOTAL);

    prep_codebook_kernel<<<256, 256>>>(emb);
    vq_main_kernel<<<NCTA, NTHREADS, SMEM_TOTAL>>>(h, emb, out);
    finalize_kernel<<<1, 256>>>(out);
}